// round 5
// baseline (speedup 1.0000x reference)
#include <cuda_runtime.h>

// Problem dims
#define NB   64      // batch
#define TE   128     // encoder steps
#define TD   64      // decoder steps
#define DE   512     // embedding dim
#define HHH  1024    // hidden (enc == dec)
#define G3   3072    // 3*H
#define DV   32000   // vocab

// ------------------------------- scratch (static device globals; no runtime alloc)
__device__ float g_gi_enc[(size_t)TE * NB * G3];   // (t, b, 3072)  100.7 MB
__device__ float g_gi_dec[(size_t)TD * NB * G3];   // (t, b, 3072)   50.3 MB
__device__ float g_gic[NB * G3];                   // ctx @ Wih_c^T
__device__ float g_states[(size_t)TD * NB * HHH];  // decoder states (t,b,H)
__device__ float g_hbuf[2][NB * HHH];              // hidden double buffer

// ------------------------------- helpers
__device__ __forceinline__ unsigned f2tf(float f) {
    unsigned u;
    asm("cvt.rna.tf32.f32 %0, %1;" : "=r"(u) : "f"(f));
    return u;
}

__device__ __forceinline__ void mma8(float* c, const unsigned* a, const unsigned* b) {
    asm volatile(
        "mma.sync.aligned.m16n8k8.row.col.f32.tf32.tf32.f32 "
        "{%0,%1,%2,%3}, {%4,%5,%6,%7}, {%8,%9}, {%0,%1,%2,%3};\n"
        : "+f"(c[0]), "+f"(c[1]), "+f"(c[2]), "+f"(c[3])
        : "r"(a[0]), "r"(a[1]), "r"(a[2]), "r"(a[3]), "r"(b[0]), "r"(b[1]));
}

// ------------------------------- big GEMM: C[M,N] = A[M,K] * B[N,K]^T (+bias)
// MODE 0: enc gi  (A-rows gathered from enc_emb via x tokens)
// MODE 1: dec gi word part (gather from dec_emb via bos/labels)
// MODE 2: logits  (A = states, scatter-store to (b,t,v) layout)
// MODE 3: ctx gi  (A = e_final, M=64 with guards, B col offset)
template <int MODE>
__global__ __launch_bounds__(128) void gemm_big(
    const float* __restrict__ A, const int* __restrict__ tok,
    const int* __restrict__ bosp, const float* __restrict__ Bw,
    int ldb, int bcol, const float* __restrict__ bias,
    float* __restrict__ C, int M, int N, int K)
{
    __shared__ unsigned As[128][36];
    __shared__ unsigned Bs[128][36];

    const int tid  = threadIdx.x;
    const int lane = tid & 31;
    const int warp = tid >> 5;
    const int wm = warp >> 1, wn = warp & 1;          // 2x2 warp grid, 64x64 tiles
    const int g = lane >> 2, t4 = lane & 3;
    const int bm0 = blockIdx.y * 128, bn0 = blockIdx.x * 128;

    float acc[4][8][4];
#pragma unroll
    for (int i = 0; i < 4; i++)
#pragma unroll
        for (int j = 0; j < 8; j++)
#pragma unroll
            for (int q = 0; q < 4; q++) acc[i][j][q] = 0.f;

    for (int k0 = 0; k0 < K; k0 += 32) {
        // ---- stage A tile 128x32 (tf32 converted)
#pragma unroll
        for (int i = 0; i < 8; i++) {
            int idx = tid + 128 * i;
            int row = idx >> 3, c4 = idx & 7;
            int gm = bm0 + row;
            float4 v = make_float4(0.f, 0.f, 0.f, 0.f);
            if (MODE == 3) {
                if (gm < M) v = *(const float4*)(A + (size_t)gm * K + k0 + c4 * 4);
            } else if (MODE == 2) {
                v = *(const float4*)(A + (size_t)gm * K + k0 + c4 * 4);
            } else {
                int t = gm >> 6, b = gm & 63;
                int token;
                if (MODE == 0) token = tok[b * TE + t];
                else           token = (t == 0) ? bosp[0] : tok[b * TD + t - 1];
                v = *(const float4*)(A + (size_t)token * DE + k0 + c4 * 4);
            }
            uint4 u;
            u.x = f2tf(v.x); u.y = f2tf(v.y); u.z = f2tf(v.z); u.w = f2tf(v.w);
            *(uint4*)&As[row][c4 * 4] = u;
        }
        // ---- stage B tile 128x32
#pragma unroll
        for (int i = 0; i < 8; i++) {
            int idx = tid + 128 * i;
            int row = idx >> 3, c4 = idx & 7;
            int gn = bn0 + row;
            float4 v = *(const float4*)(Bw + (size_t)gn * ldb + bcol + k0 + c4 * 4);
            uint4 u;
            u.x = f2tf(v.x); u.y = f2tf(v.y); u.z = f2tf(v.z); u.w = f2tf(v.w);
            *(uint4*)&Bs[row][c4 * 4] = u;
        }
        __syncthreads();

#pragma unroll
        for (int kc = 0; kc < 4; kc++) {
            const int ko = kc * 8 + t4;
            unsigned a[4][4], bb[8][2];
#pragma unroll
            for (int mt = 0; mt < 4; mt++) {
                int r = wm * 64 + mt * 16 + g;
                a[mt][0] = As[r][ko];
                a[mt][1] = As[r + 8][ko];
                a[mt][2] = As[r][ko + 4];
                a[mt][3] = As[r + 8][ko + 4];
            }
#pragma unroll
            for (int nt = 0; nt < 8; nt++) {
                int rn = wn * 64 + nt * 8 + g;
                bb[nt][0] = Bs[rn][ko];
                bb[nt][1] = Bs[rn][ko + 4];
            }
#pragma unroll
            for (int mt = 0; mt < 4; mt++)
#pragma unroll
                for (int nt = 0; nt < 8; nt++)
                    mma8(acc[mt][nt], a[mt], bb[nt]);
        }
        __syncthreads();
    }

    // ---- epilogue
#pragma unroll
    for (int mt = 0; mt < 4; mt++) {
#pragma unroll
        for (int half = 0; half < 2; half++) {
            int r = bm0 + wm * 64 + mt * 16 + g + half * 8;
            if (MODE == 3 && r >= M) continue;
#pragma unroll
            for (int nt = 0; nt < 8; nt++) {
                int c = bn0 + wn * 64 + nt * 8 + 2 * t4;
                float v0 = acc[mt][nt][half * 2 + 0];
                float v1 = acc[mt][nt][half * 2 + 1];
                if (bias) { v0 += bias[c]; v1 += bias[c + 1]; }
                size_t off;
                if (MODE == 2) {
                    int t = r >> 6, b = r & 63;
                    off = ((size_t)(b * TD + t)) * DV + c;   // out[b][t][v]
                } else {
                    off = (size_t)r * N + c;
                }
                *(float2*)(C + off) = make_float2(v0, v1);
            }
        }
    }
}

// ------------------------------- fused GRU step
// grid = 64 CTAs; CTA j owns h columns [16j,16j+16) -> 48 Whh rows (r/z/n).
// 8 warps K-split (K=1024, 4 phases of 256, 32 per warp per phase),
// tf32 MMA on SMEM-staged tiles, SMEM tree reduction, fused gate math.
#define AW 260
#define STEP_SMEM ((64 * AW + 48 * AW) * 4)  // 116480 B (Cs 98304 B reuses it)

template <int DEC>
__global__ __launch_bounds__(256) void gru_step(
    const float* __restrict__ hprev, float* __restrict__ hnext,
    const float* __restrict__ Whh, const float* __restrict__ bhh,
    const float* __restrict__ gi, const float* __restrict__ gic,
    float* __restrict__ stateout)
{
    extern __shared__ char sm_raw[];
    unsigned* As = (unsigned*)sm_raw;           // [64][260]
    unsigned* Bs = As + 64 * AW;                // [48][260]
    float* Cs = (float*)sm_raw;                 // [8][64][48], reused after compute

    const int tid  = threadIdx.x;
    const int lane = tid & 31;
    const int warp = tid >> 5;
    const int g = lane >> 2, t4 = lane & 3;
    const int c0 = blockIdx.x * 16;

    float acc[4][6][4];
#pragma unroll
    for (int i = 0; i < 4; i++)
#pragma unroll
        for (int j = 0; j < 6; j++)
#pragma unroll
            for (int q = 0; q < 4; q++) acc[i][j][q] = 0.f;

    for (int p = 0; p < 4; p++) {
        // stage A = h[64 x 256]
#pragma unroll
        for (int i = 0; i < 16; i++) {
            int idx = tid + 256 * i;
            int row = idx >> 6, c4 = idx & 63;
            float4 v = *(const float4*)(hprev + row * HHH + p * 256 + c4 * 4);
            uint4 u;
            u.x = f2tf(v.x); u.y = f2tf(v.y); u.z = f2tf(v.z); u.w = f2tf(v.w);
            *(uint4*)&As[row * AW + c4 * 4] = u;
        }
        // stage B = Whh rows {g*1024 + c0 + jj} x 256
#pragma unroll
        for (int i = 0; i < 12; i++) {
            int idx = tid + 256 * i;
            int row = idx >> 6, c4 = idx & 63;
            int gidx = row >> 4, jj = row & 15;
            int grow = gidx * HHH + c0 + jj;
            float4 v = *(const float4*)(Whh + (size_t)grow * HHH + p * 256 + c4 * 4);
            uint4 u;
            u.x = f2tf(v.x); u.y = f2tf(v.y); u.z = f2tf(v.z); u.w = f2tf(v.w);
            *(uint4*)&Bs[row * AW + c4 * 4] = u;
        }
        __syncthreads();

#pragma unroll
        for (int kc = 0; kc < 4; kc++) {
            const int ko = warp * 32 + kc * 8 + t4;
            unsigned a[4][4], bb[6][2];
#pragma unroll
            for (int mt = 0; mt < 4; mt++) {
                int r = mt * 16 + g;
                a[mt][0] = As[r * AW + ko];
                a[mt][1] = As[(r + 8) * AW + ko];
                a[mt][2] = As[r * AW + ko + 4];
                a[mt][3] = As[(r + 8) * AW + ko + 4];
            }
#pragma unroll
            for (int nt = 0; nt < 6; nt++) {
                int rn = nt * 8 + g;
                bb[nt][0] = Bs[rn * AW + ko];
                bb[nt][1] = Bs[rn * AW + ko + 4];
            }
#pragma unroll
            for (int mt = 0; mt < 4; mt++)
#pragma unroll
                for (int nt = 0; nt < 6; nt++)
                    mma8(acc[mt][nt], a[mt], bb[nt]);
        }
        __syncthreads();
    }

    // partials -> SMEM
#pragma unroll
    for (int mt = 0; mt < 4; mt++)
#pragma unroll
        for (int nt = 0; nt < 6; nt++)
#pragma unroll
            for (int q = 0; q < 4; q++) {
                int m = mt * 16 + g + (q >> 1) * 8;
                int n = nt * 8 + 2 * t4 + (q & 1);
                Cs[(warp * 64 + m) * 48 + n] = acc[mt][nt][q];
            }
    __syncthreads();

    // reduce 8 warps + GRU gate math; 1024 outputs, 4 per thread
#pragma unroll
    for (int q = 0; q < 4; q++) {
        int o = tid + 256 * q;
        int b = o >> 4, jj = o & 15;
        float sr = 0.f, sz = 0.f, sn = 0.f;
#pragma unroll
        for (int w = 0; w < 8; w++) {
            const float* cw = Cs + (w * 64 + b) * 48;
            sr += cw[jj]; sz += cw[16 + jj]; sn += cw[32 + jj];
        }
        int col = c0 + jj;
        float gir = gi[b * G3 + col];
        float giz = gi[b * G3 + 1024 + col];
        float gin = gi[b * G3 + 2048 + col];
        if (DEC) {
            gir += gic[b * G3 + col];
            giz += gic[b * G3 + 1024 + col];
            gin += gic[b * G3 + 2048 + col];
        }
        sr += bhh[col];
        sz += bhh[1024 + col];
        sn += bhh[2048 + col];
        float r = 1.f / (1.f + __expf(-(gir + sr)));
        float z = 1.f / (1.f + __expf(-(giz + sz)));
        float nn = tanhf(gin + r * sn);
        float hp = hprev[b * HHH + col];
        float hN = (1.f - z) * nn + z * hp;
        hnext[b * HHH + col] = hN;
        if (DEC) stateout[b * HHH + col] = hN;
    }
}

// init / broadcast hidden state
__global__ void init_h_kernel(float* dst, const float* src) {
    int i = blockIdx.x * 256 + threadIdx.x;
    dst[i] = src ? src[i & (HHH - 1)] : 0.f;
}

// ------------------------------- launch
extern "C" void kernel_launch(void* const* d_in, const int* in_sizes, int n_in,
                              void* d_out, int out_size)
{
    const int*   x        = (const int*)d_in[0];
    const int*   labels   = (const int*)d_in[1];
    const int*   bosp     = (const int*)d_in[2];
    const float* enc_emb  = (const float*)d_in[3];
    const float* enc_Wih  = (const float*)d_in[4];
    const float* enc_Whh  = (const float*)d_in[5];
    const float* enc_bih  = (const float*)d_in[6];
    const float* enc_bhh  = (const float*)d_in[7];
    const float* dec_emb  = (const float*)d_in[8];
    const float* dec_Wih  = (const float*)d_in[9];
    const float* dec_Whh  = (const float*)d_in[10];
    const float* dec_bih  = (const float*)d_in[11];
    const float* dec_bhh  = (const float*)d_in[12];
    const float* dec_init = (const float*)d_in[13];
    const float* lin_W    = (const float*)d_in[14];
    const float* lin_b    = (const float*)d_in[15];
    float* out = (float*)d_out;

    float *p_gi_enc, *p_gi_dec, *p_gic, *p_states, *p_h;
    cudaGetSymbolAddress((void**)&p_gi_enc, g_gi_enc);
    cudaGetSymbolAddress((void**)&p_gi_dec, g_gi_dec);
    cudaGetSymbolAddress((void**)&p_gic,    g_gic);
    cudaGetSymbolAddress((void**)&p_states, g_states);
    cudaGetSymbolAddress((void**)&p_h,      g_hbuf);
    float* h0 = p_h;
    float* h1 = p_h + NB * HHH;

    cudaFuncSetAttribute(gru_step<0>, cudaFuncAttributeMaxDynamicSharedMemorySize, STEP_SMEM);
    cudaFuncSetAttribute(gru_step<1>, cudaFuncAttributeMaxDynamicSharedMemorySize, STEP_SMEM);

    // encoder gi for all steps: (8192 x 3072) = emb_gather(8192x512) * enc_Wih^T + bih
    init_h_kernel<<<NB * HHH / 256, 256>>>(h0, nullptr);
    gemm_big<0><<<dim3(G3 / 128, TE * NB / 128), 128>>>(
        enc_emb, x, nullptr, enc_Wih, DE, 0, enc_bih, p_gi_enc, TE * NB, G3, DE);

    // encoder recurrence
    for (int t = 0; t < TE; t++) {
        float* hp = (t & 1) ? h1 : h0;
        float* hn = (t & 1) ? h0 : h1;
        gru_step<0><<<64, 256, STEP_SMEM>>>(hp, hn, enc_Whh, enc_bhh,
                                            p_gi_enc + (size_t)t * NB * G3,
                                            nullptr, nullptr);
    }
    // e_final is in h0 (t=127 writes h0)

    // ctx contribution: (64 x 3072) = e_final(64x1024) * dec_Wih[:,512:]^T
    gemm_big<3><<<dim3(G3 / 128, 1), 128>>>(
        h0, nullptr, nullptr, dec_Wih, DE + HHH, DE, nullptr, p_gic, NB, G3, HHH);

    // decoder word-part gi for all steps
    gemm_big<1><<<dim3(G3 / 128, TD * NB / 128), 128>>>(
        dec_emb, labels, bosp, dec_Wih, DE + HHH, 0, dec_bih, p_gi_dec, TD * NB, G3, DE);

    // decoder recurrence
    init_h_kernel<<<NB * HHH / 256, 256>>>(h0, dec_init);
    for (int t = 0; t < TD; t++) {
        float* hp = (t & 1) ? h1 : h0;
        float* hn = (t & 1) ? h0 : h1;
        gru_step<1><<<64, 256, STEP_SMEM>>>(hp, hn, dec_Whh, dec_bhh,
                                            p_gi_dec + (size_t)t * NB * G3,
                                            p_gic,
                                            p_states + (size_t)t * NB * HHH);
    }

    // logits: (4096 x 32000) = states * lin_W^T + lin_b, scattered to (b,t,v)
    gemm_big<2><<<dim3(DV / 128, TD * NB / 128), 128>>>(
        p_states, nullptr, nullptr, lin_W, HHH, 0, lin_b, out, TD * NB, DV, HHH);
}

// round 6
// speedup vs baseline: 1.1558x; 1.1558x over previous
#include <cuda_runtime.h>

// Problem dims
#define NB   64      // batch
#define TE   128     // encoder steps
#define TD   64      // decoder steps
#define DE   512     // embedding dim
#define HHH  1024    // hidden (enc == dec)
#define G3   3072    // 3*H
#define DV   32000   // vocab

#define GRID_P 64    // persistent CTAs (all co-resident: 64 <= 148 SMs, 1 CTA/SM)

// ------------------------------- scratch (static device globals; no runtime alloc)
__device__ float g_gi_enc[(size_t)TE * NB * G3];   // (t, b, 3072)
__device__ float g_gi_dec[(size_t)TD * NB * G3];   // (t, b, 3072)
__device__ float g_gic[NB * G3];                   // ctx @ Wih_c^T
__device__ float g_states[(size_t)TD * NB * HHH];  // decoder states (t,b,H)
__device__ float g_hbuf[2][NB * HHH];              // hidden double buffer
__device__ unsigned g_bar;                         // grid barrier counter

// ------------------------------- helpers
__device__ __forceinline__ unsigned f2tf(float f) {
    unsigned u;
    asm("cvt.rna.tf32.f32 %0, %1;" : "=r"(u) : "f"(f));
    return u;
}

__device__ __forceinline__ void mma8(float* c, const unsigned* a, const unsigned* b) {
    asm volatile(
        "mma.sync.aligned.m16n8k8.row.col.f32.tf32.tf32.f32 "
        "{%0,%1,%2,%3}, {%4,%5,%6,%7}, {%8,%9}, {%0,%1,%2,%3};\n"
        : "+f"(c[0]), "+f"(c[1]), "+f"(c[2]), "+f"(c[3])
        : "r"(a[0]), "r"(a[1]), "r"(a[2]), "r"(a[3]), "r"(b[0]), "r"(b[1]));
}

// ------------------------------- big GEMM: C[M,N] = A[M,K] * B[N,K]^T (+bias)
// MODE 0: enc gi (gather enc_emb via x)   MODE 1: dec gi word part
// MODE 2: logits (scatter to (b,t,v))     MODE 3: ctx gi (M=64, B col offset)
template <int MODE>
__global__ __launch_bounds__(128) void gemm_big(
    const float* __restrict__ A, const int* __restrict__ tok,
    const int* __restrict__ bosp, const float* __restrict__ Bw,
    int ldb, int bcol, const float* __restrict__ bias,
    float* __restrict__ C, int M, int N, int K)
{
    __shared__ unsigned As[128][36];
    __shared__ unsigned Bs[128][36];

    const int tid  = threadIdx.x;
    const int lane = tid & 31;
    const int warp = tid >> 5;
    const int wm = warp >> 1, wn = warp & 1;
    const int g = lane >> 2, t4 = lane & 3;
    const int bm0 = blockIdx.y * 128, bn0 = blockIdx.x * 128;

    float acc[4][8][4];
#pragma unroll
    for (int i = 0; i < 4; i++)
#pragma unroll
        for (int j = 0; j < 8; j++)
#pragma unroll
            for (int q = 0; q < 4; q++) acc[i][j][q] = 0.f;

    for (int k0 = 0; k0 < K; k0 += 32) {
#pragma unroll
        for (int i = 0; i < 8; i++) {
            int idx = tid + 128 * i;
            int row = idx >> 3, c4 = idx & 7;
            int gm = bm0 + row;
            float4 v = make_float4(0.f, 0.f, 0.f, 0.f);
            if (MODE == 3) {
                if (gm < M) v = *(const float4*)(A + (size_t)gm * K + k0 + c4 * 4);
            } else if (MODE == 2) {
                v = *(const float4*)(A + (size_t)gm * K + k0 + c4 * 4);
            } else {
                int t = gm >> 6, b = gm & 63;
                int token;
                if (MODE == 0) token = tok[b * TE + t];
                else           token = (t == 0) ? bosp[0] : tok[b * TD + t - 1];
                v = *(const float4*)(A + (size_t)token * DE + k0 + c4 * 4);
            }
            uint4 u;
            u.x = f2tf(v.x); u.y = f2tf(v.y); u.z = f2tf(v.z); u.w = f2tf(v.w);
            *(uint4*)&As[row][c4 * 4] = u;
        }
#pragma unroll
        for (int i = 0; i < 8; i++) {
            int idx = tid + 128 * i;
            int row = idx >> 3, c4 = idx & 7;
            int gn = bn0 + row;
            float4 v = *(const float4*)(Bw + (size_t)gn * ldb + bcol + k0 + c4 * 4);
            uint4 u;
            u.x = f2tf(v.x); u.y = f2tf(v.y); u.z = f2tf(v.z); u.w = f2tf(v.w);
            *(uint4*)&Bs[row][c4 * 4] = u;
        }
        __syncthreads();

#pragma unroll
        for (int kc = 0; kc < 4; kc++) {
            const int ko = kc * 8 + t4;
            unsigned a[4][4], bb[8][2];
#pragma unroll
            for (int mt = 0; mt < 4; mt++) {
                int r = wm * 64 + mt * 16 + g;
                a[mt][0] = As[r][ko];
                a[mt][1] = As[r + 8][ko];
                a[mt][2] = As[r][ko + 4];
                a[mt][3] = As[r + 8][ko + 4];
            }
#pragma unroll
            for (int nt = 0; nt < 8; nt++) {
                int rn = wn * 64 + nt * 8 + g;
                bb[nt][0] = Bs[rn][ko];
                bb[nt][1] = Bs[rn][ko + 4];
            }
#pragma unroll
            for (int mt = 0; mt < 4; mt++)
#pragma unroll
                for (int nt = 0; nt < 8; nt++)
                    mma8(acc[mt][nt], a[mt], bb[nt]);
        }
        __syncthreads();
    }

#pragma unroll
    for (int mt = 0; mt < 4; mt++) {
#pragma unroll
        for (int half = 0; half < 2; half++) {
            int r = bm0 + wm * 64 + mt * 16 + g + half * 8;
            if (MODE == 3 && r >= M) continue;
#pragma unroll
            for (int nt = 0; nt < 8; nt++) {
                int c = bn0 + wn * 64 + nt * 8 + 2 * t4;
                float v0 = acc[mt][nt][half * 2 + 0];
                float v1 = acc[mt][nt][half * 2 + 1];
                if (bias) { v0 += bias[c]; v1 += bias[c + 1]; }
                size_t off;
                if (MODE == 2) {
                    int t = r >> 6, b = r & 63;
                    off = ((size_t)(b * TD + t)) * DV + c;
                } else {
                    off = (size_t)r * N + c;
                }
                *(float2*)(C + off) = make_float2(v0, v1);
            }
        }
    }
}

// ------------------------------- persistent GRU recurrence
// 64 CTAs, 256 threads. CTA j owns h columns [16j,16j+16) -> 48 Whh rows,
// kept RESIDENT in SMEM as tf32 for the whole recurrence (read from DRAM once).
// Per step: stage h (tf32) in 8 phases of 128 cols with register prefetch,
// 8-warp interleaved K-split MMA, 4-round staged reduction into a 2-region
// SMEM buffer, fused gate math (hprev carried in registers), then a grid-wide
// atomic barrier. h is exchanged between CTAs via global ping-pong buffers
// read with __ldcg (L2-coherent, bypasses stale L1).
#define BSTR 1028                              // Whh smem stride (words)
#define ASTR 132                               // h tile smem stride (words)
#define PSMEM (48 * BSTR * 4 + 64 * ASTR * 4)  // 197376 + 33792 = 231168 B

template <int DEC>
__global__ __launch_bounds__(256) void gru_persist(
    float* __restrict__ hA, float* __restrict__ hB,
    const float* __restrict__ Whh, const float* __restrict__ bhh,
    const float* __restrict__ gi, const float* __restrict__ gic,
    float* __restrict__ states, int T)
{
    extern __shared__ char sm_raw[];
    unsigned* Bs = (unsigned*)sm_raw;                       // [48][1028] tf32 Whh
    unsigned* As = (unsigned*)(sm_raw + 48 * BSTR * 4);     // [64][132] h phase tile
    float*    Cs = (float*)(sm_raw + 48 * BSTR * 4);        // [2][64][50] (reuses As)

    const int tid  = threadIdx.x;
    const int lane = tid & 31;
    const int warp = tid >> 5;
    const int g = lane >> 2, t4 = lane & 3;
    const int c0 = blockIdx.x * 16;

    // ---- load Whh slice into SMEM once (48 rows x 1024, tf32)
    for (int i = tid; i < 48 * 256; i += 256) {
        int row = i >> 8, c4 = i & 255;
        int grow = (row >> 4) * HHH + c0 + (row & 15);       // gate-major rows
        float4 v = *(const float4*)(Whh + (size_t)grow * HHH + c4 * 4);
        uint4 u;
        u.x = f2tf(v.x); u.y = f2tf(v.y); u.z = f2tf(v.z); u.w = f2tf(v.w);
        *(uint4*)&Bs[row * BSTR + c4 * 4] = u;
    }

    // ---- per-thread output constants: bhh (+gic), initial h in registers
    int ob[4], jj4[4];
    float cr[4], cz[4], cn[4], hN[4];
#pragma unroll
    for (int q = 0; q < 4; q++) {
        int o = tid + 256 * q;
        int b = o >> 4, jj = o & 15, col = c0 + jj;
        ob[q] = b; jj4[q] = jj;
        float a0 = bhh[col], a1 = bhh[1024 + col], a2 = bhh[2048 + col];
        if (DEC) {
            a0 += gic[b * G3 + col];
            a1 += gic[b * G3 + 1024 + col];
            a2 += gic[b * G3 + 2048 + col];
        }
        cr[q] = a0; cz[q] = a1; cn[q] = a2;
        hN[q] = hA[b * HHH + col];
    }

    const int r0  = tid >> 5;   // staging row base
    const int sc4 = tid & 31;   // staging float4 column

    float* hp = hA;
    float* hn = hB;
    unsigned target = 0;

#pragma unroll 1
    for (int t = 0; t < T; t++) {
        // prefetch this step's gi slice (consumed ~4000 cyc later in gates)
        const float* giT = gi + (size_t)t * NB * G3;
        float pr[4], pz[4], pn[4];
#pragma unroll
        for (int q = 0; q < 4; q++) {
            int b = ob[q], col = c0 + jj4[q];
            pr[q] = giT[b * G3 + col];
            pz[q] = giT[b * G3 + 1024 + col];
            pn[q] = giT[b * G3 + 2048 + col];
        }

        float acc[4][6][4];
#pragma unroll
        for (int i = 0; i < 4; i++)
#pragma unroll
            for (int j = 0; j < 6; j++)
#pragma unroll
                for (int q = 0; q < 4; q++) acc[i][j][q] = 0.f;

        // prefetch phase 0 of h into registers (L2-coherent)
        float4 pf[8];
#pragma unroll
        for (int j = 0; j < 8; j++)
            pf[j] = __ldcg((const float4*)(hp + (r0 + 8 * j) * HHH + sc4 * 4));

#pragma unroll 1
        for (int p = 0; p < 8; p++) {
            __syncthreads();                  // As free
#pragma unroll
            for (int j = 0; j < 8; j++) {
                uint4 u;
                u.x = f2tf(pf[j].x); u.y = f2tf(pf[j].y);
                u.z = f2tf(pf[j].z); u.w = f2tf(pf[j].w);
                *(uint4*)&As[(r0 + 8 * j) * ASTR + sc4 * 4] = u;
            }
            __syncthreads();                  // As ready
            if (p < 7) {
#pragma unroll
                for (int j = 0; j < 8; j++)
                    pf[j] = __ldcg((const float4*)(hp + (r0 + 8 * j) * HHH +
                                                   (p + 1) * 128 + sc4 * 4));
            }
            // MMA: warp w handles k-chunk [w*16, w*16+16) within this phase
#pragma unroll
            for (int kc2 = 0; kc2 < 2; kc2++) {
                const int ko = warp * 16 + kc2 * 8 + t4;
                unsigned a[4][4], bb[6][2];
#pragma unroll
                for (int mt = 0; mt < 4; mt++) {
                    int r = mt * 16 + g;
                    a[mt][0] = As[r * ASTR + ko];
                    a[mt][1] = As[(r + 8) * ASTR + ko];
                    a[mt][2] = As[r * ASTR + ko + 4];
                    a[mt][3] = As[(r + 8) * ASTR + ko + 4];
                }
#pragma unroll
                for (int nt = 0; nt < 6; nt++) {
                    int rn = nt * 8 + g;
                    bb[nt][0] = Bs[rn * BSTR + p * 128 + ko];
                    bb[nt][1] = Bs[rn * BSTR + p * 128 + ko + 4];
                }
#pragma unroll
                for (int mt = 0; mt < 4; mt++)
#pragma unroll
                    for (int nt = 0; nt < 6; nt++)
                        mma8(acc[mt][nt], a[mt], bb[nt]);
            }
        }

        // ---- staged reduction 8 warps -> 2 regions
        __syncthreads();
        if (warp < 2) {
            float* C = Cs + (warp & 1) * (64 * 50);
#pragma unroll
            for (int mt = 0; mt < 4; mt++)
#pragma unroll
                for (int nt = 0; nt < 6; nt++) {
                    int m0 = mt * 16 + g, n0 = nt * 8 + 2 * t4;
                    *(float2*)&C[m0 * 50 + n0] =
                        make_float2(acc[mt][nt][0], acc[mt][nt][1]);
                    *(float2*)&C[(m0 + 8) * 50 + n0] =
                        make_float2(acc[mt][nt][2], acc[mt][nt][3]);
                }
        }
        __syncthreads();
#pragma unroll 1
        for (int rr = 1; rr < 4; rr++) {
            if ((warp >> 1) == rr) {
                float* C = Cs + (warp & 1) * (64 * 50);
#pragma unroll
                for (int mt = 0; mt < 4; mt++)
#pragma unroll
                    for (int nt = 0; nt < 6; nt++) {
                        int m0 = mt * 16 + g, n0 = nt * 8 + 2 * t4;
                        float2 v0 = *(float2*)&C[m0 * 50 + n0];
                        v0.x += acc[mt][nt][0]; v0.y += acc[mt][nt][1];
                        *(float2*)&C[m0 * 50 + n0] = v0;
                        float2 v1 = *(float2*)&C[(m0 + 8) * 50 + n0];
                        v1.x += acc[mt][nt][2]; v1.y += acc[mt][nt][3];
                        *(float2*)&C[(m0 + 8) * 50 + n0] = v1;
                    }
            }
            __syncthreads();
        }

        // ---- gate math (hprev carried in hN registers)
#pragma unroll
        for (int q = 0; q < 4; q++) {
            int b = ob[q], jj = jj4[q];
            const float* C0 = Cs + b * 50;
            const float* C1 = Cs + 64 * 50 + b * 50;
            float sr = C0[jj]      + C1[jj];
            float sz = C0[16 + jj] + C1[16 + jj];
            float sn = C0[32 + jj] + C1[32 + jj];
            float r  = 1.f / (1.f + __expf(-(pr[q] + cr[q] + sr)));
            float z  = 1.f / (1.f + __expf(-(pz[q] + cz[q] + sz)));
            float nv = tanhf(pn[q] + cn[q] + r * sn);
            hN[q] = (1.f - z) * nv + z * hN[q];
            int col = c0 + jj;
            hn[b * HHH + col] = hN[q];
            if (DEC)
                states[(size_t)t * NB * HHH + b * HHH + col] = hN[q];
        }

        // ---- grid-wide barrier (monotonic counter; reset by init kernel)
        target += GRID_P;
        __syncthreads();
        if (tid == 0) {
            __threadfence();                  // publish hn stores (release)
            atomicAdd(&g_bar, 1u);
            unsigned v;
            do {
                asm volatile("ld.acquire.gpu.u32 %0, [%1];"
                             : "=r"(v) : "l"(&g_bar) : "memory");
            } while (v < target);
        }
        __syncthreads();

        float* tmp = hp; hp = hn; hn = tmp;
    }
}

// init hidden buffer + reset grid-barrier counter
__global__ void init_h_kernel(float* dst, const float* src) {
    int i = blockIdx.x * 256 + threadIdx.x;
    if (i == 0) g_bar = 0u;
    dst[i] = src ? src[i & (HHH - 1)] : 0.f;
}

// ------------------------------- launch
extern "C" void kernel_launch(void* const* d_in, const int* in_sizes, int n_in,
                              void* d_out, int out_size)
{
    const int*   x        = (const int*)d_in[0];
    const int*   labels   = (const int*)d_in[1];
    const int*   bosp     = (const int*)d_in[2];
    const float* enc_emb  = (const float*)d_in[3];
    const float* enc_Wih  = (const float*)d_in[4];
    const float* enc_Whh  = (const float*)d_in[5];
    const float* enc_bih  = (const float*)d_in[6];
    const float* enc_bhh  = (const float*)d_in[7];
    const float* dec_emb  = (const float*)d_in[8];
    const float* dec_Wih  = (const float*)d_in[9];
    const float* dec_Whh  = (const float*)d_in[10];
    const float* dec_bih  = (const float*)d_in[11];
    const float* dec_bhh  = (const float*)d_in[12];
    const float* dec_init = (const float*)d_in[13];
    const float* lin_W    = (const float*)d_in[14];
    const float* lin_b    = (const float*)d_in[15];
    float* out = (float*)d_out;

    float *p_gi_enc, *p_gi_dec, *p_gic, *p_states, *p_h;
    cudaGetSymbolAddress((void**)&p_gi_enc, g_gi_enc);
    cudaGetSymbolAddress((void**)&p_gi_dec, g_gi_dec);
    cudaGetSymbolAddress((void**)&p_gic,    g_gic);
    cudaGetSymbolAddress((void**)&p_states, g_states);
    cudaGetSymbolAddress((void**)&p_h,      g_hbuf);
    float* h0 = p_h;
    float* h1 = p_h + NB * HHH;

    cudaFuncSetAttribute(gru_persist<0>, cudaFuncAttributeMaxDynamicSharedMemorySize, PSMEM);
    cudaFuncSetAttribute(gru_persist<1>, cudaFuncAttributeMaxDynamicSharedMemorySize, PSMEM);

    // encoder gi for all steps: (8192 x 3072)
    init_h_kernel<<<NB * HHH / 256, 256>>>(h0, nullptr);
    gemm_big<0><<<dim3(G3 / 128, TE * NB / 128), 128>>>(
        enc_emb, x, nullptr, enc_Wih, DE, 0, enc_bih, p_gi_enc, TE * NB, G3, DE);

    // encoder recurrence: one persistent launch, 128 steps
    gru_persist<0><<<GRID_P, 256, PSMEM>>>(h0, h1, enc_Whh, enc_bhh,
                                           p_gi_enc, nullptr, nullptr, TE);
    // e_final lands in h0 (last step t=127 is odd -> writes h0)

    // ctx contribution: (64 x 3072) = e_final * dec_Wih[:,512:]^T
    gemm_big<3><<<dim3(G3 / 128, 1), 128>>>(
        h0, nullptr, nullptr, dec_Wih, DE + HHH, DE, nullptr, p_gic, NB, G3, HHH);

    // decoder word-part gi for all steps
    gemm_big<1><<<dim3(G3 / 128, TD * NB / 128), 128>>>(
        dec_emb, labels, bosp, dec_Wih, DE + HHH, 0, dec_bih, p_gi_dec, TD * NB, G3, DE);

    // decoder recurrence: one persistent launch, 64 steps
    init_h_kernel<<<NB * HHH / 256, 256>>>(h0, dec_init);   // also resets g_bar
    gru_persist<1><<<GRID_P, 256, PSMEM>>>(h0, h1, dec_Whh, dec_bhh,
                                           p_gi_dec, p_gic, p_states, TD);

    // logits: (4096 x 32000) scattered to (b,t,v)
    gemm_big<2><<<dim3(DV / 128, TD * NB / 128), 128>>>(
        p_states, nullptr, nullptr, lin_W, HHH, 0, lin_b, out, TD * NB, DV, HHH);
}